// round 8
// baseline (speedup 1.0000x reference)
#include <cuda_runtime.h>
#include <cuda_fp16.h>
#include <mma.h>
#include <cstdint>

using namespace nvcuda;

// Problem constants
#define Bb 8
#define Cc 64
#define Nn 500
#define Tt 12
#define Hh 4
#define Ff 64
#define Ss (Bb * Tt)   // 96 slices (b,t)
#define HF (Hh * Ff)   // 256
#define MAXD 128
#define ALPHAc 0.05f
#define LEAKc 0.2f

// ---------------- scratch (device globals; no allocation) ----------------
__device__ float   g_xT[Ss * Nn * Cc];                   // [s,n,c] fp32 (final path)
__device__ __half  g_xT16[Ss * Nn * Cc];                 // fp16 iterates
__device__ __half  g_h1T16[Ss * Nn * Cc];
__device__ __half  g_h2T16[Ss * Nn * Cc];
__device__ __half  g_Wh16[(size_t)Ss * Nn * HF];         // [s,n,hf] fp16
__device__ float   g_e1[Ss * Hh * Nn];                   // [(s*H+h)*N + n]
__device__ float   g_e2[Ss * Hh * Nn];
__device__ __half  g_Wcat16[Cc * HF];                    // [c, h*F+f] fp16
__device__ __half  g_WgT16[HF * Cc];                     // [hf, o] fp16
__device__ float   g_WmT[3 * Cc * Cc];                   // [c_global, o]
__device__ int     g_cnt[Nn];
__device__ int     g_nbr[Nn * MAXD];

// ================= merged prep: nbr list + weight layouts + input transpose =========
__global__ void prep_all(const float* __restrict__ adj,
                         const float* __restrict__ W,
                         const float* __restrict__ Wg,
                         const float* __restrict__ Wm,
                         const float* __restrict__ x,
                         float* __restrict__ xT) {
    __shared__ float sm[16][193];
    const int blk = blockIdx.x;
    if (blk < 125) {
        if (threadIdx.x >= 128) return;
        int warp = threadIdx.x >> 5;
        int lane = threadIdx.x & 31;
        int n = blk * 4 + warp;
        if (n >= Nn) return;
        int base = 0;
        for (int m0 = 0; m0 < 512; m0 += 32) {
            int m = m0 + lane;
            bool p = (m < Nn) && (adj[n * Nn + m] > 0.f || m == n);
            unsigned mask = __ballot_sync(0xffffffffu, p);
            if (p) {
                int r = __popc(mask & ((1u << lane) - 1));
                if (base + r < MAXD) g_nbr[n * MAXD + base + r] = m;
            }
            base += __popc(mask);
        }
        if (lane == 0) g_cnt[n] = base < MAXD ? base : MAXD;
    } else if (blk < 189) {
        int i = (blk - 125) * 256 + threadIdx.x;
        if (i < Hh * Cc * Ff) {  // Wcat16[c, h*F+f] = W[h,c,f]
            int f = i % Ff; int rest = i / Ff;
            int c = rest % Cc; int h = rest / Cc;
            g_Wcat16[c * HF + h * Ff + f] = __float2half_rn(W[(h * Cc + c) * Ff + f]);
        }
        if (i < HF * Cc) {       // WgT16[hf, o] = half(Wg[o, hf])
            int o = i % Cc; int hf = i / Cc;
            g_WgT16[hf * Cc + o] = __float2half_rn(Wg[o * HF + hf]);
        }
        if (i < 3 * Cc * Cc) {   // WmT[c, o] = Wm[o, c]
            int o = i % Cc; int c = i / Cc;
            g_WmT[c * Cc + o] = Wm[o * (3 * Cc) + c];
        }
    } else {
        // transpose: x[b,c,n,t] -> xT[s,n,c] (fp32 + fp16)
        if (threadIdx.x >= 192) return;
        const int bi = blk - 189;
        const int nb = bi & 31, cb = (bi >> 5) & 3, b = bi >> 7;
        const int c0 = cb * 16, n0 = nb * 16;
        const int tt_ = threadIdx.x;
        const int ni_l = tt_ / 12, tl = tt_ % 12;
        const int n_l = n0 + ni_l;
        #pragma unroll
        for (int ci = 0; ci < 16; ++ci) {
            float v = 0.f;
            if (n_l < Nn)
                v = x[(((size_t)b * Cc + c0 + ci) * Nn + n_l) * Tt + tl];
            sm[ci][tt_] = v;
        }
        __syncthreads();
        #pragma unroll
        for (int rep = 0; rep < 16; ++rep) {
            int idx = rep * 192 + tt_;
            int ci = idx & 15;
            int rest = idx >> 4;
            int ni = rest / 12, t = rest % 12;
            int n = n0 + ni;
            if (n < Nn) {
                size_t oi = (((size_t)(b * Tt + t) * Nn) + n) * Cc + c0 + ci;
                float v = sm[ci][rest];
                xT[oi] = v;
                g_xT16[oi] = __float2half_rn(v);
            }
        }
    }
}

// ================= fp16 HMMA projection GEMM (2 heads/block) + e1/e2 + Wh ===========
// grid (Ss, 8, 2), block 256 (8 warps). Tile 64 rows x 128 cols (heads 2z, 2z+1), K=64.
#define PAS_LD 72
#define PBS_LD 136
#define PCS_LD 132
__global__ void gemm_proj16(const __half* __restrict__ Ain,
                            const float* __restrict__ a1,
                            const float* __restrict__ a2) {
    __shared__ __align__(16) char smemRaw[64 * PCS_LD * 4];      // 33792 B
    __half (*As)[PAS_LD] = (__half(*)[PAS_LD])smemRaw;           // 9216 B
    __half (*Bs)[PBS_LD] = (__half(*)[PBS_LD])(smemRaw + 64 * PAS_LD * 2); // 17408 B
    float (*Cs)[PCS_LD] = (float(*)[PCS_LD])smemRaw;             // reuse after MMA

    const int s = blockIdx.x;
    const int r0 = blockIdx.y * 64;
    const int z = blockIdx.z;            // head pair
    const int c0 = z * 128;
    const int tid = threadIdx.x;
    const int wid = tid >> 5;
    const int wm = wid & 3, wn = wid >> 2;   // rows wm*16, cols wn*64

    // stage A: 64 rows x 64 halfs (8 uint4/row), 2 uint4/thread
    {
        const uint4* srcA = (const uint4*)(Ain + (size_t)s * Nn * Cc);
        #pragma unroll
        for (int k = 0; k < 2; ++k) {
            int idx = k * 256 + tid;
            int r = idx >> 3, p = idx & 7;
            int row = r0 + r;
            uint4 v = make_uint4(0, 0, 0, 0);
            if (row < Nn) v = srcA[(size_t)row * 8 + p];
            *(uint4*)&As[r][p * 8] = v;
        }
    }
    // stage B: Wcat16 rows 0..63, cols c0..c0+127 (16 uint4/row), 4 uint4/thread
    {
        const uint4* srcB = (const uint4*)(g_Wcat16 + c0);
        #pragma unroll
        for (int k = 0; k < 4; ++k) {
            int idx = k * 256 + tid;
            int r = idx >> 4, p = idx & 15;
            *(uint4*)&Bs[r][p * 8] = srcB[r * 32 + p];   // row stride 256 half = 32 uint4
        }
    }
    __syncthreads();

    wmma::fragment<wmma::accumulator, 16, 16, 16, float> fc[4];
    #pragma unroll
    for (int j = 0; j < 4; ++j) wmma::fill_fragment(fc[j], 0.f);
    #pragma unroll
    for (int k0 = 0; k0 < 64; k0 += 16) {
        wmma::fragment<wmma::matrix_a, 16, 16, 16, __half, wmma::row_major> fa;
        wmma::load_matrix_sync(fa, &As[wm * 16][k0], PAS_LD);
        #pragma unroll
        for (int j = 0; j < 4; ++j) {
            wmma::fragment<wmma::matrix_b, 16, 16, 16, __half, wmma::row_major> fb;
            wmma::load_matrix_sync(fb, &Bs[k0][wn * 64 + j * 16], PBS_LD);
            wmma::mma_sync(fc[j], fa, fb, fc[j]);
        }
    }
    __syncthreads();   // done reading As/Bs; reuse as Cs
    #pragma unroll
    for (int j = 0; j < 4; ++j)
        wmma::store_matrix_sync(&Cs[wm * 16][wn * 64 + j * 16], fc[j], PCS_LD,
                                wmma::mem_row_major);
    __syncthreads();

    // fused e1/e2 for both heads: thread -> row tid>>2, quarter q = tid&3 (16 cols/head)
    {
        const int row = tid >> 2, q = tid & 3;
        #pragma unroll
        for (int hh = 0; hh < 2; ++hh) {
            const int hg = z * 2 + hh;           // global head
            float s1 = 0.f, s2 = 0.f;
            #pragma unroll
            for (int i = 0; i < 16; ++i) {
                int cl = hh * 64 + q * 16 + i;
                float v = Cs[row][cl];
                s1 = fmaf(v, a1[hg * Ff + q * 16 + i], s1);
                s2 = fmaf(v, a2[hg * Ff + q * 16 + i], s2);
            }
            s1 += __shfl_xor_sync(0xffffffffu, s1, 1);
            s2 += __shfl_xor_sync(0xffffffffu, s2, 1);
            s1 += __shfl_xor_sync(0xffffffffu, s1, 2);
            s2 += __shfl_xor_sync(0xffffffffu, s2, 2);
            if (q == 0 && r0 + row < Nn) {
                const int sh = s * Hh + hg;
                g_e1[sh * Nn + r0 + row] = s1;
                g_e2[sh * Nn + r0 + row] = s2;
            }
        }
    }

    // fp16 Wh store (coalesced): 64 rows x 64 half2
    __half2* dst = (__half2*)g_Wh16;
    #pragma unroll
    for (int k = 0; k < 16; ++k) {
        int idx = k * 256 + tid;
        int r = idx >> 6, p = idx & 63;
        if (r0 + r < Nn) {
            dst[((size_t)s * Nn + r0 + r) * (HF / 2) + z * 64 + p] =
                __floats2half2_rn(Cs[r][2 * p], Cs[r][2 * p + 1]);
        }
    }
}

// ================= FUSED attention + mix GEMM ======================================
// grid (8, Ss), block 256 (8 warps). Tile: 64 nodes of slice s.
// Phase A: warp-per-node softmax (4 heads) + uint4 gather -> hprS smem fp16 tile.
// Phase B: 64x64 HMMA: h_next16 = a*x16 + (1-a)*(hprS @ WgT16 + bg).
#define HPR_LD 264
__global__ __launch_bounds__(256)
void attn_mix(const float* __restrict__ bias,
              const __half* __restrict__ resid16,
              __half* __restrict__ Cm16) {
    __shared__ __align__(16) char smemRaw[64 * HPR_LD * 2];   // 33792 B; hprS then Cs
    __shared__ __half swS[8][MAXD][4];                        // 8192 B softmax weights
    __half (*hprS)[HPR_LD] = (__half(*)[HPR_LD])smemRaw;
    float (*Cs)[68] = (float(*)[68])smemRaw;

    const int r0 = blockIdx.x * 64;
    const int s = blockIdx.y;
    const int tid = threadIdx.x;
    const int wid = tid >> 5;
    const int lane = tid & 31;
    const size_t rowB = (size_t)s * Nn;

    // ---------- Phase A: attention, warp per node ----------
    for (int rr = wid; rr < 64; rr += 8) {
        const int n = r0 + rr;
        if (n >= Nn) {
            // zero the A row (keeps GEMM deterministic)
            for (int p = lane; p < HPR_LD / 2; p += 32)
                ((uint32_t*)hprS[rr])[p] = 0;
            continue;
        }
        const int cnt = min(g_cnt[n], MAXD);
        int mv[4];
        #pragma unroll
        for (int k = 0; k < 4; ++k)
            mv[k] = (k * 32 + lane < cnt) ? g_nbr[n * MAXD + k * 32 + lane] : 0;

        // softmax per head
        #pragma unroll
        for (int h = 0; h < Hh; ++h) {
            const int sh = s * Hh + h;
            const float e1v = g_e1[sh * Nn + n];
            const float* e2r = g_e2 + (size_t)sh * Nn;
            float ev[4];
            float mx = -1e30f;
            #pragma unroll
            for (int k = 0; k < 4; ++k) {
                int j = k * 32 + lane;
                float e = -1e30f;
                if (j < cnt) {
                    float tv = e1v + e2r[mv[k]];
                    e = tv > 0.f ? tv : LEAKc * tv;
                }
                ev[k] = e;
                mx = fmaxf(mx, e);
            }
            #pragma unroll
            for (int o = 16; o; o >>= 1) mx = fmaxf(mx, __shfl_xor_sync(0xffffffffu, mx, o));
            float sum = 0.f;
            #pragma unroll
            for (int k = 0; k < 4; ++k) {
                float w = (k * 32 + lane < cnt) ? __expf(ev[k] - mx) : 0.f;
                ev[k] = w;
                sum += w;
            }
            #pragma unroll
            for (int o = 16; o; o >>= 1) sum += __shfl_xor_sync(0xffffffffu, sum, o);
            const float inv = 1.f / sum;
            #pragma unroll
            for (int k = 0; k < 4; ++k) {
                int j = k * 32 + lane;
                if (j < cnt) swS[wid][j][h] = __float2half_rn(ev[k] * inv);
            }
        }
        __syncwarp();

        // gather: lane owns 16B chunk `lane` of the 512B row; head = lane>>3
        const int hc = lane >> 3;
        const uint4* Whv = (const uint4*)g_Wh16;
        float acc[8] = {};
        for (int j = 0; j < cnt; ++j) {
            int m = __shfl_sync(0xffffffffu, mv[j >> 5], j & 31);
            float w = __half2float(swS[wid][j][hc]);
            uint4 v = Whv[(rowB + m) * 32 + lane];
            float2 f0 = __half22float2(*(__half2*)&v.x);
            float2 f1 = __half22float2(*(__half2*)&v.y);
            float2 f2 = __half22float2(*(__half2*)&v.z);
            float2 f3 = __half22float2(*(__half2*)&v.w);
            acc[0] = fmaf(w, f0.x, acc[0]); acc[1] = fmaf(w, f0.y, acc[1]);
            acc[2] = fmaf(w, f1.x, acc[2]); acc[3] = fmaf(w, f1.y, acc[3]);
            acc[4] = fmaf(w, f2.x, acc[4]); acc[5] = fmaf(w, f2.y, acc[5]);
            acc[6] = fmaf(w, f3.x, acc[6]); acc[7] = fmaf(w, f3.y, acc[7]);
        }
        // elu + pack to smem A tile
        __half2 pk[4];
        #pragma unroll
        for (int i = 0; i < 4; ++i) {
            float vx = acc[2 * i],     vy = acc[2 * i + 1];
            vx = vx > 0.f ? vx : (__expf(vx) - 1.f);
            vy = vy > 0.f ? vy : (__expf(vy) - 1.f);
            pk[i] = __floats2half2_rn(vx, vy);
        }
        *(uint4*)&hprS[rr][lane * 8] = *(uint4*)pk;
    }
    __syncthreads();

    // ---------- Phase B: mix GEMM (A = hprS smem, B = WgT16 global/L2) ----------
    const int wm = wid & 3, wn = wid >> 2;
    wmma::fragment<wmma::accumulator, 16, 16, 16, float> fc[2];
    wmma::fill_fragment(fc[0], 0.f);
    wmma::fill_fragment(fc[1], 0.f);
    #pragma unroll
    for (int k0 = 0; k0 < HF; k0 += 16) {
        wmma::fragment<wmma::matrix_a, 16, 16, 16, __half, wmma::row_major> fa;
        wmma::load_matrix_sync(fa, &hprS[wm * 16][k0], HPR_LD);
        #pragma unroll
        for (int sub = 0; sub < 2; ++sub) {
            wmma::fragment<wmma::matrix_b, 16, 16, 16, __half, wmma::row_major> fb;
            wmma::load_matrix_sync(fb, &g_WgT16[k0 * Cc + wn * 32 + sub * 16], Cc);
            wmma::mma_sync(fc[sub], fa, fb, fc[sub]);
        }
    }
    __syncthreads();   // all warps done reading hprS; reuse as Cs
    wmma::store_matrix_sync(&Cs[wm * 16][wn * 32], fc[0], 68, wmma::mem_row_major);
    wmma::store_matrix_sync(&Cs[wm * 16][wn * 32 + 16], fc[1], 68, wmma::mem_row_major);
    __syncthreads();

    #pragma unroll
    for (int k = 0; k < 16; ++k) {
        int idx = k * 256 + tid;
        int r = idx >> 6, c = idx & 63;
        int row = r0 + r;
        if (row < Nn) {
            size_t oidx = (rowB + row) * Cc + c;
            float v = ALPHAc * __half2float(resid16[oidx])
                    + (1.f - ALPHAc) * (Cs[r][c] + bias[c]);
            Cm16[oidx] = __float2half_rn(v);
        }
    }
}

// ---------------- final: out[b,o,n,t] = bm[o] + Wm @ [x; h1; h2] ----------------
__global__ void final_out(const float* __restrict__ xT,
                          const __half* __restrict__ h1,
                          const __half* __restrict__ h2,
                          const float* __restrict__ bm,
                          float* __restrict__ out) {
    __shared__ float sX[16][64], sH1[16][64], sH2[16][64];
    const int s = blockIdx.x;
    const int n0 = blockIdx.y * 16;
    const int tid = threadIdx.x;
    for (int i = tid; i < 16 * 64; i += 256) {
        int nl = i >> 6, c = i & 63;
        int n = n0 + nl;
        size_t idx = ((size_t)s * Nn + (n < Nn ? n : 0)) * Cc + c;
        sX[nl][c]  = (n < Nn) ? xT[idx] : 0.f;
        sH1[nl][c] = (n < Nn) ? __half2float(h1[idx]) : 0.f;
        sH2[nl][c] = (n < Nn) ? __half2float(h2[idx]) : 0.f;
    }
    __syncthreads();
    const int o = tid & 63, ng = tid >> 6;
    float acc[4] = {0.f, 0.f, 0.f, 0.f};
    #pragma unroll 4
    for (int c = 0; c < 64; ++c) {
        float w0 = g_WmT[c * Cc + o];
        float w1 = g_WmT[(64 + c) * Cc + o];
        float w2 = g_WmT[(128 + c) * Cc + o];
        #pragma unroll
        for (int r = 0; r < 4; ++r) {
            int nl = ng + r * 4;
            acc[r] = fmaf(w0, sX[nl][c], fmaf(w1, sH1[nl][c], fmaf(w2, sH2[nl][c], acc[r])));
        }
    }
    const int b = s / Tt, t = s % Tt;
    const float bias = bm[o];
    #pragma unroll
    for (int r = 0; r < 4; ++r) {
        int n = n0 + ng + r * 4;
        if (n < Nn)
            out[(((size_t)b * Cc + o) * Nn + n) * Tt + t] = acc[r] + bias;
    }
}

// ---------------- launch ----------------
extern "C" void kernel_launch(void* const* d_in, const int* in_sizes, int n_in,
                              void* d_out, int out_size) {
    const float* x   = (const float*)d_in[0];
    const float* adj = (const float*)d_in[1];
    const float* W   = (const float*)d_in[2];
    const float* a1  = (const float*)d_in[3];
    const float* a2  = (const float*)d_in[4];
    const float* Wg  = (const float*)d_in[5];
    const float* bg  = (const float*)d_in[6];
    const float* Wm  = (const float*)d_in[7];
    const float* bm  = (const float*)d_in[8];
    float* out = (float*)d_out;

    float* xT;
    __half *xT16, *h1T16, *h2T16;
    cudaGetSymbolAddress((void**)&xT,    g_xT);
    cudaGetSymbolAddress((void**)&xT16,  g_xT16);
    cudaGetSymbolAddress((void**)&h1T16, g_h1T16);
    cudaGetSymbolAddress((void**)&h2T16, g_h2T16);

    prep_all<<<1213, 256>>>(adj, W, Wg, Wm, x, xT);

    const __half* hin16 = xT16;
    __half* hb16[2] = {h1T16, h2T16};
    for (int it = 0; it < 2; ++it) {
        gemm_proj16<<<dim3(Ss, 8, 2), 256>>>(hin16, a1, a2);
        attn_mix<<<dim3(8, Ss), 256>>>(bg, xT16, hb16[it]);
        hin16 = hb16[it];
    }
    final_out<<<dim3(Ss, (Nn + 15) / 16), 256>>>(xT, h1T16, h2T16, bm, out);
}

// round 9
// speedup vs baseline: 1.0517x; 1.0517x over previous
#include <cuda_runtime.h>
#include <cuda_fp16.h>
#include <mma.h>
#include <cstdint>

using namespace nvcuda;

// Problem constants
#define Bb 8
#define Cc 64
#define Nn 500
#define Tt 12
#define Hh 4
#define Ff 64
#define Ss (Bb * Tt)   // 96 slices (b,t)
#define HF (Hh * Ff)   // 256
#define MAXD 128
#define ALPHAc 0.05f
#define OMAc 0.95f
#define LEAKc 0.2f

// ---------------- scratch (device globals; no allocation) ----------------
__device__ __half  g_xT16[Ss * Nn * Cc];                 // [s,n,c] fp16
__device__ __half  g_WhA16[(size_t)Ss * Nn * HF];        // Wh iter0 (= x@Wcat)
__device__ __half  g_WhB16[(size_t)Ss * Nn * HF];        // Wh iter1
__device__ __half  g_hprA16[(size_t)Ss * Nn * HF];       // hpr iter0
__device__ __half  g_hprB16[(size_t)Ss * Nn * HF];       // hpr iter1
__device__ float   g_e1v[Ss * Nn * 4];                   // [(s*N+n)*4 + h]
__device__ float   g_e2v[Ss * Nn * 4];
__device__ __half  g_Wcat16[Cc * HF];                    // [c, h*F+f]
__device__ __half  g_M16[HF * HF];                       // (1-a)*WgT@Wcat [hf][j]
__device__ float   g_bgW[HF];                            // (1-a)*bg@Wcat
__device__ __half  g_A1T16[HF * Cc];                     // (1-a)*(Wm2@Wg)^T [hf][o]
__device__ __half  g_A2T16[HF * Cc];
__device__ __half  g_Wx16[Cc * Cc];                      // [c][o]
__device__ float   g_bmp[Cc];
__device__ int     g_cnt[Nn];
__device__ int     g_nbr[Nn * MAXD];

// ================= merged prep =========
// [0,125): nbr | [125,189): Wcat16 | [189,445): M16 | 445/446: A1T/A2T |
// 447: Wx,bgW,bmp | [448,1472): transpose
__global__ void prep_all(const float* __restrict__ adj,
                         const float* __restrict__ W,
                         const float* __restrict__ Wg,
                         const float* __restrict__ Wm,
                         const float* __restrict__ bg,
                         const float* __restrict__ bm,
                         const float* __restrict__ x) {
    __shared__ float sm[16][193];
    const int blk = blockIdx.x;
    const int tid = threadIdx.x;
    if (blk < 125) {
        if (tid >= 128) return;
        int warp = tid >> 5, lane = tid & 31;
        int n = blk * 4 + warp;
        if (n >= Nn) return;
        int base = 0;
        for (int m0 = 0; m0 < 512; m0 += 32) {
            int m = m0 + lane;
            bool p = (m < Nn) && (adj[n * Nn + m] > 0.f || m == n);
            unsigned mask = __ballot_sync(0xffffffffu, p);
            if (p) {
                int r = __popc(mask & ((1u << lane) - 1));
                if (base + r < MAXD) g_nbr[n * MAXD + base + r] = m;
            }
            base += __popc(mask);
        }
        if (lane == 0) g_cnt[n] = base < MAXD ? base : MAXD;
    } else if (blk < 189) {
        int i = (blk - 125) * 256 + tid;   // 16384 entries
        int f = i % Ff; int rest = i / Ff;
        int c = rest % Cc; int h = rest / Cc;
        g_Wcat16[c * HF + h * Ff + f] = __float2half_rn(W[(h * Cc + c) * Ff + f]);
    } else if (blk < 445) {
        // M[hf][j] = (1-a) * sum_c Wg[c*HF+hf] * W[(jh*64+c)*64+jf]
        const int hf = blk - 189;
        float* wgcol = (float*)sm;
        if (tid < Cc) wgcol[tid] = Wg[tid * HF + hf];
        __syncthreads();
        const int j = tid, jh = j >> 6, jf = j & 63;
        float acc = 0.f;
        #pragma unroll 8
        for (int c = 0; c < Cc; ++c)
            acc = fmaf(wgcol[c], W[(jh * 64 + c) * 64 + jf], acc);
        g_M16[hf * HF + j] = __float2half_rn(OMAc * acc);
    } else if (blk < 447) {
        // A_iT[hf][o] = (1-a) * sum_c Wm[o*192 + 64*i + c] * Wg[c*HF+hf]
        const int i = blk - 444;            // 1 or 2
        const int hf = tid;
        __half* dst = (i == 1) ? g_A1T16 : g_A2T16;
        for (int o = 0; o < Cc; ++o) {
            float acc = 0.f;
            #pragma unroll 8
            for (int c = 0; c < Cc; ++c)
                acc = fmaf(Wm[o * (3 * Cc) + 64 * i + c], Wg[c * HF + hf], acc);
            dst[hf * Cc + o] = __float2half_rn(OMAc * acc);
        }
    } else if (blk == 447) {
        // Wx16[c][o] = Wm[o][c] + a*(Wm[o][64+c]+Wm[o][128+c])
        for (int idx = tid; idx < Cc * Cc; idx += 256) {
            int o = idx & 63, c = idx >> 6;
            float v = Wm[o * (3 * Cc) + c]
                    + ALPHAc * (Wm[o * (3 * Cc) + 64 + c] + Wm[o * (3 * Cc) + 128 + c]);
            g_Wx16[c * Cc + o] = __float2half_rn(v);
        }
        // bgW[j] = (1-a) * sum_c bg[c]*W[(jh*64+c)*64+jf]
        if (tid < HF) {
            int jh = tid >> 6, jf = tid & 63;
            float acc = 0.f;
            for (int c = 0; c < Cc; ++c)
                acc = fmaf(bg[c], W[(jh * 64 + c) * 64 + jf], acc);
            g_bgW[tid] = OMAc * acc;
        }
        // bmp[o] = bm[o] + (1-a)*sum_c (Wm[o][64+c]+Wm[o][128+c])*bg[c]
        if (tid < Cc) {
            float acc = 0.f;
            for (int c = 0; c < Cc; ++c)
                acc = fmaf(Wm[tid * (3 * Cc) + 64 + c] + Wm[tid * (3 * Cc) + 128 + c],
                           bg[c], acc);
            g_bmp[tid] = bm[tid] + OMAc * acc;
        }
    } else {
        // transpose: x[b,c,n,t] -> xT16[s,n,c]
        if (tid >= 192) return;
        const int bi = blk - 448;
        const int nb = bi & 31, cb = (bi >> 5) & 3, b = bi >> 7;
        const int c0 = cb * 16, n0 = nb * 16;
        const int ni_l = tid / 12, tl = tid % 12;
        const int n_l = n0 + ni_l;
        #pragma unroll
        for (int ci = 0; ci < 16; ++ci) {
            float v = 0.f;
            if (n_l < Nn)
                v = x[(((size_t)b * Cc + c0 + ci) * Nn + n_l) * Tt + tl];
            sm[ci][tid] = v;
        }
        __syncthreads();
        #pragma unroll
        for (int rep = 0; rep < 16; ++rep) {
            int idx = rep * 192 + tid;
            int ci = idx & 15;
            int rest = idx >> 4;
            int ni = rest / 12, t = rest % 12;
            int n = n0 + ni;
            if (n < Nn)
                g_xT16[(((size_t)(b * Tt + t) * Nn) + n) * Cc + c0 + ci] =
                    __float2half_rn(sm[ci][rest]);
        }
    }
}

// ================= proj0: WhA = x16 @ Wcat16 (2 heads/block) + e-vec ================
#define PAS_LD 72
#define PBS_LD 136
#define PCS_LD 132
__global__ void gemm_proj16(const __half* __restrict__ Ain,
                            __half* __restrict__ WhOut,
                            const float* __restrict__ a1,
                            const float* __restrict__ a2) {
    __shared__ __align__(16) char smemRaw[64 * PCS_LD * 4];
    __half (*As)[PAS_LD] = (__half(*)[PAS_LD])smemRaw;
    __half (*Bs)[PBS_LD] = (__half(*)[PBS_LD])(smemRaw + 64 * PAS_LD * 2);
    float (*Cs)[PCS_LD] = (float(*)[PCS_LD])smemRaw;

    const int s = blockIdx.x;
    const int r0 = blockIdx.y * 64;
    const int z = blockIdx.z;
    const int c0 = z * 128;
    const int tid = threadIdx.x;
    const int wid = tid >> 5;
    const int wm = wid & 3, wn = wid >> 2;
    const size_t rowB = (size_t)s * Nn;

    {
        const uint4* srcA = (const uint4*)(Ain + rowB * Cc);
        #pragma unroll
        for (int k = 0; k < 2; ++k) {
            int idx = k * 256 + tid;
            int r = idx >> 3, p = idx & 7;
            int row = r0 + r;
            uint4 v = make_uint4(0, 0, 0, 0);
            if (row < Nn) v = srcA[(size_t)row * 8 + p];
            *(uint4*)&As[r][p * 8] = v;
        }
    }
    {
        const uint4* srcB = (const uint4*)(g_Wcat16 + c0);
        #pragma unroll
        for (int k = 0; k < 4; ++k) {
            int idx = k * 256 + tid;
            int r = idx >> 4, p = idx & 15;
            *(uint4*)&Bs[r][p * 8] = srcB[r * 32 + p];
        }
    }
    __syncthreads();

    wmma::fragment<wmma::accumulator, 16, 16, 16, float> fc[4];
    #pragma unroll
    for (int j = 0; j < 4; ++j) wmma::fill_fragment(fc[j], 0.f);
    #pragma unroll
    for (int k0 = 0; k0 < 64; k0 += 16) {
        wmma::fragment<wmma::matrix_a, 16, 16, 16, __half, wmma::row_major> fa;
        wmma::load_matrix_sync(fa, &As[wm * 16][k0], PAS_LD);
        #pragma unroll
        for (int j = 0; j < 4; ++j) {
            wmma::fragment<wmma::matrix_b, 16, 16, 16, __half, wmma::row_major> fb;
            wmma::load_matrix_sync(fb, &Bs[k0][wn * 64 + j * 16], PBS_LD);
            wmma::mma_sync(fc[j], fa, fb, fc[j]);
        }
    }
    __syncthreads();
    #pragma unroll
    for (int j = 0; j < 4; ++j)
        wmma::store_matrix_sync(&Cs[wm * 16][wn * 64 + j * 16], fc[j], PCS_LD,
                                wmma::mem_row_major);
    __syncthreads();

    // e-vec: thread -> row tid>>2, quarter q=tid&3 (16 cols/head); reduce 4 lanes
    {
        const int row = tid >> 2, q = tid & 3;
        #pragma unroll
        for (int hh = 0; hh < 2; ++hh) {
            const int hg = z * 2 + hh;
            float s1 = 0.f, s2 = 0.f;
            #pragma unroll
            for (int i = 0; i < 16; ++i) {
                float v = Cs[row][hh * 64 + q * 16 + i];
                s1 = fmaf(v, a1[hg * Ff + q * 16 + i], s1);
                s2 = fmaf(v, a2[hg * Ff + q * 16 + i], s2);
            }
            s1 += __shfl_xor_sync(0xffffffffu, s1, 1);
            s2 += __shfl_xor_sync(0xffffffffu, s2, 1);
            s1 += __shfl_xor_sync(0xffffffffu, s1, 2);
            s2 += __shfl_xor_sync(0xffffffffu, s2, 2);
            if (q == 0 && r0 + row < Nn) {
                g_e1v[(rowB + r0 + row) * 4 + hg] = s1;
                g_e2v[(rowB + r0 + row) * 4 + hg] = s2;
            }
        }
    }

    // fp16 Wh store: 64 rows x 64 half2
    __half2* dst = (__half2*)WhOut;
    #pragma unroll
    for (int k = 0; k < 16; ++k) {
        int idx = k * 256 + tid;
        int r = idx >> 6, p = idx & 63;
        if (r0 + r < Nn) {
            dst[(rowB + r0 + r) * (HF / 2) + z * 64 + p] =
                __floats2half2_rn(Cs[r][2 * p], Cs[r][2 * p + 1]);
        }
    }
}

// ---------------- attention: block (n,s), 128 thr; float4 e layout ----------------
__global__ void attn_agg(const __half* __restrict__ Wh,
                         __half* __restrict__ hprOut) {
    const int n = blockIdx.x, s = blockIdx.y;
    const int t = threadIdx.x;
    const int h = t >> 5, lane = t & 31;
    __shared__ int snbr[MAXD];
    __shared__ float sw[Hh][MAXD];
    __shared__ float sred[4][HF];

    const int cnt = min(g_cnt[n], MAXD);
    for (int j = t; j < cnt; j += 128) snbr[j] = g_nbr[n * MAXD + j];
    __syncthreads();

    const size_t rowB = (size_t)s * Nn;
    const float e1v = g_e1v[(rowB + n) * 4 + h];
    float ev[4];
    float mx = -1e30f;
    #pragma unroll
    for (int k = 0; k < 4; ++k) {
        int j = k * 32 + lane;
        float e = -1e30f;
        if (j < cnt) {
            float tv = e1v + g_e2v[(rowB + snbr[j]) * 4 + h];
            e = tv > 0.f ? tv : LEAKc * tv;
        }
        ev[k] = e;
        mx = fmaxf(mx, e);
    }
    #pragma unroll
    for (int o = 16; o; o >>= 1) mx = fmaxf(mx, __shfl_xor_sync(0xffffffffu, mx, o));
    float sum = 0.f;
    #pragma unroll
    for (int k = 0; k < 4; ++k) {
        float w = (k * 32 + lane < cnt) ? __expf(ev[k] - mx) : 0.f;
        ev[k] = w;
        sum += w;
    }
    #pragma unroll
    for (int o = 16; o; o >>= 1) sum += __shfl_xor_sync(0xffffffffu, sum, o);
    const float inv = 1.f / sum;
    #pragma unroll
    for (int k = 0; k < 4; ++k) {
        int j = k * 32 + lane;
        if (j < cnt) sw[h][j] = ev[k] * inv;
    }
    __syncthreads();

    // gather: thread (g=t>>5, c=t&31); chunk c = 16B of the 512B row
    const int g = t >> 5, c = t & 31;
    const int hc = c >> 3;
    const uint4* Whv = (const uint4*)Wh;
    float acc[8] = {};
    #pragma unroll 2
    for (int j0 = 0; j0 < cnt; j0 += 4) {
        int j = j0 + g;
        if (j < cnt) {
            int m = snbr[j];
            float w = sw[hc][j];
            uint4 v = Whv[(rowB + m) * 32 + c];
            float2 f0 = __half22float2(*(__half2*)&v.x);
            float2 f1 = __half22float2(*(__half2*)&v.y);
            float2 f2 = __half22float2(*(__half2*)&v.z);
            float2 f3 = __half22float2(*(__half2*)&v.w);
            acc[0] = fmaf(w, f0.x, acc[0]); acc[1] = fmaf(w, f0.y, acc[1]);
            acc[2] = fmaf(w, f1.x, acc[2]); acc[3] = fmaf(w, f1.y, acc[3]);
            acc[4] = fmaf(w, f2.x, acc[4]); acc[5] = fmaf(w, f2.y, acc[5]);
            acc[6] = fmaf(w, f3.x, acc[6]); acc[7] = fmaf(w, f3.y, acc[7]);
        }
    }
    #pragma unroll
    for (int i = 0; i < 8; ++i) sred[g][c * 8 + i] = acc[i];
    __syncthreads();

    float vx = sred[0][2 * t]     + sred[1][2 * t]     + sred[2][2 * t]     + sred[3][2 * t];
    float vy = sred[0][2 * t + 1] + sred[1][2 * t + 1] + sred[2][2 * t + 1] + sred[3][2 * t + 1];
    vx = vx > 0.f ? vx : (__expf(vx) - 1.f);
    vy = vy > 0.f ? vy : (__expf(vy) - 1.f);
    ((__half2*)hprOut)[(rowB + n) * (HF / 2) + t] = __floats2half2_rn(vx, vy);
}

// ================= mixproj: WhB = a*WhA + hprA@M' + bgW' (+ e-vec) ==================
// grid (Ss, 8, 2), block 256. Tile 64 rows x 128 cols, K=256 in 4 chunks.
__global__ void mixproj(const __half* __restrict__ hpr,
                        const __half* __restrict__ WhA,
                        __half* __restrict__ WhB,
                        const float* __restrict__ a1,
                        const float* __restrict__ a2) {
    __shared__ __align__(16) char smemRaw[64 * PCS_LD * 4];      // 33792
    __half (*As)[PAS_LD] = (__half(*)[PAS_LD])smemRaw;           // 9216
    __half (*Bs)[PBS_LD] = (__half(*)[PBS_LD])(smemRaw + 64 * PAS_LD * 2); // 17408
    float (*Cs)[PCS_LD] = (float(*)[PCS_LD])smemRaw;

    const int s = blockIdx.x;
    const int r0 = blockIdx.y * 64;
    const int z = blockIdx.z;
    const int c0 = z * 128;
    const int tid = threadIdx.x;
    const int wid = tid >> 5;
    const int wm = wid & 3, wn = wid >> 2;
    const size_t rowB = (size_t)s * Nn;

    wmma::fragment<wmma::accumulator, 16, 16, 16, float> fc[4];
    #pragma unroll
    for (int j = 0; j < 4; ++j) wmma::fill_fragment(fc[j], 0.f);

    for (int kb = 0; kb < HF; kb += 64) {
        // stage A chunk: rows 64 x cols kb..kb+63
        {
            const uint4* srcA = (const uint4*)hpr;
            #pragma unroll
            for (int k = 0; k < 2; ++k) {
                int idx = k * 256 + tid;
                int r = idx >> 3, p = idx & 7;
                int row = r0 + r;
                uint4 v = make_uint4(0, 0, 0, 0);
                if (row < Nn) v = srcA[(rowB + row) * 32 + (kb >> 3) + p];
                *(uint4*)&As[r][p * 8] = v;
            }
        }
        // stage B chunk: M16[kb..kb+63][c0..c0+127]
        {
            const uint4* srcB = (const uint4*)(g_M16 + c0);
            #pragma unroll
            for (int k = 0; k < 4; ++k) {
                int idx = k * 256 + tid;
                int r = idx >> 4, p = idx & 15;
                *(uint4*)&Bs[r][p * 8] = srcB[(size_t)(kb + r) * 32 + p];
            }
        }
        __syncthreads();
        #pragma unroll
        for (int k0 = 0; k0 < 64; k0 += 16) {
            wmma::fragment<wmma::matrix_a, 16, 16, 16, __half, wmma::row_major> fa;
            wmma::load_matrix_sync(fa, &As[wm * 16][k0], PAS_LD);
            #pragma unroll
            for (int j = 0; j < 4; ++j) {
                wmma::fragment<wmma::matrix_b, 16, 16, 16, __half, wmma::row_major> fb;
                wmma::load_matrix_sync(fb, &Bs[k0][wn * 64 + j * 16], PBS_LD);
                wmma::mma_sync(fc[j], fa, fb, fc[j]);
            }
        }
        __syncthreads();
    }
    #pragma unroll
    for (int j = 0; j < 4; ++j)
        wmma::store_matrix_sync(&Cs[wm * 16][wn * 64 + j * 16], fc[j], PCS_LD,
                                wmma::mem_row_major);
    __syncthreads();

    // epilogue: v = a*WhA + Cs + bgW ; write WhB fp16 + update Cs for e-vec
    {
        const __half2* srcR = (const __half2*)WhA;
        __half2* dst = (__half2*)WhB;
        #pragma unroll
        for (int k = 0; k < 16; ++k) {
            int idx = k * 256 + tid;
            int r = idx >> 6, pc = idx & 63;       // pair col
            int row = r0 + r;
            if (row < Nn) {
                float2 rv = __half22float2(srcR[(rowB + row) * (HF / 2) + (c0 >> 1) + pc]);
                float v0 = ALPHAc * rv.x + Cs[r][2 * pc]     + g_bgW[c0 + 2 * pc];
                float v1 = ALPHAc * rv.y + Cs[r][2 * pc + 1] + g_bgW[c0 + 2 * pc + 1];
                Cs[r][2 * pc] = v0;
                Cs[r][2 * pc + 1] = v1;
                dst[(rowB + row) * (HF / 2) + (c0 >> 1) + pc] = __floats2half2_rn(v0, v1);
            }
        }
    }
    __syncthreads();

    // e-vec from corrected Cs
    {
        const int row = tid >> 2, q = tid & 3;
        #pragma unroll
        for (int hh = 0; hh < 2; ++hh) {
            const int hg = z * 2 + hh;
            float s1 = 0.f, s2 = 0.f;
            #pragma unroll
            for (int i = 0; i < 16; ++i) {
                float v = Cs[row][hh * 64 + q * 16 + i];
                s1 = fmaf(v, a1[hg * Ff + q * 16 + i], s1);
                s2 = fmaf(v, a2[hg * Ff + q * 16 + i], s2);
            }
            s1 += __shfl_xor_sync(0xffffffffu, s1, 1);
            s2 += __shfl_xor_sync(0xffffffffu, s2, 1);
            s1 += __shfl_xor_sync(0xffffffffu, s1, 2);
            s2 += __shfl_xor_sync(0xffffffffu, s2, 2);
            if (q == 0 && r0 + row < Nn) {
                g_e1v[(rowB + r0 + row) * 4 + hg] = s1;
                g_e2v[(rowB + r0 + row) * 4 + hg] = s2;
            }
        }
    }
}

// ================= final: out = x16@Wx + hprA@A1T + hprB@A2T + bmp ==================
// grid (Ss, 8), block 256.
#define FS_LD 72
__global__ void final_out(const __half* __restrict__ x16,
                          const __half* __restrict__ h1p,
                          const __half* __restrict__ h2p,
                          float* __restrict__ out) {
    __shared__ __align__(16) char smemRaw[2 * 64 * FS_LD * 2];   // 18432
    __half (*As)[FS_LD] = (__half(*)[FS_LD])smemRaw;
    __half (*Bs)[FS_LD] = (__half(*)[FS_LD])(smemRaw + 64 * FS_LD * 2);
    float (*Cs)[68] = (float(*)[68])smemRaw;                     // 17408 <= 18432

    const int s = blockIdx.x;
    const int r0 = blockIdx.y * 64;
    const int tid = threadIdx.x;
    const int wid = tid >> 5;
    const int wm = wid & 3, wn = wid >> 2;
    const size_t rowB = (size_t)s * Nn;

    wmma::fragment<wmma::accumulator, 16, 16, 16, float> fc[2];
    wmma::fill_fragment(fc[0], 0.f);
    wmma::fill_fragment(fc[1], 0.f);

    // 9 chunks: (x16,Wx16,K64) + (hprA,A1T,K256) + (hprB,A2T,K256)
    #pragma unroll 1
    for (int ch = 0; ch < 9; ++ch) {
        const __half* srcA; const __half* srcB; int kb; int rstride; // uint4 row stride
        if (ch == 0)      { srcA = x16; srcB = g_Wx16;  kb = 0;             rstride = 8; }
        else if (ch < 5)  { srcA = h1p; srcB = g_A1T16; kb = (ch - 1) * 64; rstride = 32; }
        else              { srcA = h2p; srcB = g_A2T16; kb = (ch - 5) * 64; rstride = 32; }
        {
            const uint4* sA = (const uint4*)srcA;
            #pragma unroll
            for (int k = 0; k < 2; ++k) {
                int idx = k * 256 + tid;
                int r = idx >> 3, p = idx & 7;
                int row = r0 + r;
                uint4 v = make_uint4(0, 0, 0, 0);
                if (row < Nn) v = sA[(rowB + row) * rstride + (kb >> 3) + p];
                *(uint4*)&As[r][p * 8] = v;
            }
            const uint4* sB = (const uint4*)srcB;
            #pragma unroll
            for (int k = 0; k < 2; ++k) {
                int idx = k * 256 + tid;
                int r = idx >> 3, p = idx & 7;
                *(uint4*)&Bs[r][p * 8] = sB[(size_t)(kb + r) * 8 + p];
            }
        }
        __syncthreads();
        #pragma unroll
        for (int k0 = 0; k0 < 64; k0 += 16) {
            wmma::fragment<wmma::matrix_a, 16, 16, 16, __half, wmma::row_major> fa;
            wmma::load_matrix_sync(fa, &As[wm * 16][k0], FS_LD);
            #pragma unroll
            for (int sub = 0; sub < 2; ++sub) {
                wmma::fragment<wmma::matrix_b, 16, 16, 16, __half, wmma::row_major> fb;
                wmma::load_matrix_sync(fb, &Bs[k0][wn * 32 + sub * 16], FS_LD);
                wmma::mma_sync(fc[sub], fa, fb, fc[sub]);
            }
        }
        __syncthreads();
    }
    wmma::store_matrix_sync(&Cs[wm * 16][wn * 32], fc[0], 68, wmma::mem_row_major);
    wmma::store_matrix_sync(&Cs[wm * 16][wn * 32 + 16], fc[1], 68, wmma::mem_row_major);
    __syncthreads();

    const int b = s / Tt, t = s % Tt;
    #pragma unroll
    for (int k = 0; k < 16; ++k) {
        int idx = k * 256 + tid;
        int r = idx >> 6, c = idx & 63;
        int row = r0 + r;
        if (row < Nn)
            out[(((size_t)b * Cc + c) * Nn + row) * Tt + t] = Cs[r][c] + g_bmp[c];
    }
}

// ---------------- launch ----------------
extern "C" void kernel_launch(void* const* d_in, const int* in_sizes, int n_in,
                              void* d_out, int out_size) {
    const float* x   = (const float*)d_in[0];
    const float* adj = (const float*)d_in[1];
    const float* W   = (const float*)d_in[2];
    const float* a1  = (const float*)d_in[3];
    const float* a2  = (const float*)d_in[4];
    const float* Wg  = (const float*)d_in[5];
    const float* bg  = (const float*)d_in[6];
    const float* Wm  = (const float*)d_in[7];
    const float* bm  = (const float*)d_in[8];
    float* out = (float*)d_out;

    __half *xT16, *WhA, *WhB, *hprA, *hprB;
    cudaGetSymbolAddress((void**)&xT16, g_xT16);
    cudaGetSymbolAddress((void**)&WhA,  g_WhA16);
    cudaGetSymbolAddress((void**)&WhB,  g_WhB16);
    cudaGetSymbolAddress((void**)&hprA, g_hprA16);
    cudaGetSymbolAddress((void**)&hprB, g_hprB16);

    prep_all<<<1472, 256>>>(adj, W, Wg, Wm, bg, bm, x);
    gemm_proj16<<<dim3(Ss, 8, 2), 256>>>(xT16, WhA, a1, a2);
    attn_agg<<<dim3(Nn, Ss), 128>>>(WhA, hprA);
    mixproj<<<dim3(Ss, 8, 2), 256>>>(hprA, WhA, WhB, a1, a2);
    attn_agg<<<dim3(Nn, Ss), 128>>>(WhB, hprB);
    final_out<<<dim3(Ss, 8), 256>>>(xT16, hprA, hprB, out);
}

// round 10
// speedup vs baseline: 1.3117x; 1.2473x over previous
#include <cuda_runtime.h>
#include <cuda_fp16.h>
#include <mma.h>
#include <cstdint>

using namespace nvcuda;

// Problem constants
#define Bb 8
#define Cc 64
#define Nn 500
#define Tt 12
#define Hh 4
#define Ff 64
#define Ss (Bb * Tt)   // 96 slices (b,t)
#define HF (Hh * Ff)   // 256
#define MAXD 128
#define ROWPAD 16
#define ALPHAc 0.05f
#define LEAKc 0.2f

// ---------------- scratch (device globals; no allocation) ----------------
__device__ float   g_xT[Ss * Nn * Cc];                   // [s,n,c] fp32 (final path)
__device__ __half  g_xT16[Ss * Nn * Cc];                 // fp16 iterates
__device__ __half  g_h1T16[Ss * Nn * Cc];
__device__ __half  g_h2T16[Ss * Nn * Cc];
__device__ __half  g_Wh16[(size_t)Ss * Nn * HF];         // [s,n,hf] fp16
__device__ __half  g_hpr16[((size_t)Ss * Nn + ROWPAD) * HF]; // padded for OOB frag rows
__device__ float   g_e1v[Ss * Nn * 4];                   // [(s*N+n)*4 + h]
__device__ float   g_e2v[Ss * Nn * 4];
__device__ __half  g_Wcat16[Cc * HF];                    // [c, h*F+f] fp16
__device__ __half  g_WgT16[HF * Cc];                     // [hf, o] fp16
__device__ float   g_WmT[3 * Cc * Cc];                   // [c_global, o]
__device__ int     g_cnt[Nn];
__device__ int     g_nbr[Nn * MAXD];

// ================= merged prep: nbr list + weight layouts + input transpose =========
__global__ void prep_all(const float* __restrict__ adj,
                         const float* __restrict__ W,
                         const float* __restrict__ Wg,
                         const float* __restrict__ Wm,
                         const float* __restrict__ x,
                         float* __restrict__ xT) {
    __shared__ float sm[16][193];
    const int blk = blockIdx.x;
    if (blk < 125) {
        if (threadIdx.x >= 128) return;
        int warp = threadIdx.x >> 5;
        int lane = threadIdx.x & 31;
        int n = blk * 4 + warp;
        if (n >= Nn) return;
        int base = 0;
        for (int m0 = 0; m0 < 512; m0 += 32) {
            int m = m0 + lane;
            bool p = (m < Nn) && (adj[n * Nn + m] > 0.f || m == n);
            unsigned mask = __ballot_sync(0xffffffffu, p);
            if (p) {
                int r = __popc(mask & ((1u << lane) - 1));
                if (base + r < MAXD) g_nbr[n * MAXD + base + r] = m;
            }
            base += __popc(mask);
        }
        if (lane == 0) g_cnt[n] = base < MAXD ? base : MAXD;
    } else if (blk < 189) {
        int i = (blk - 125) * 256 + threadIdx.x;
        if (i < Hh * Cc * Ff) {  // Wcat16[c, h*F+f] = W[h,c,f]
            int f = i % Ff; int rest = i / Ff;
            int c = rest % Cc; int h = rest / Cc;
            g_Wcat16[c * HF + h * Ff + f] = __float2half_rn(W[(h * Cc + c) * Ff + f]);
        }
        if (i < HF * Cc) {       // WgT16[hf, o] = half(Wg[o, hf])
            int o = i % Cc; int hf = i / Cc;
            g_WgT16[hf * Cc + o] = __float2half_rn(Wg[o * HF + hf]);
        }
        if (i < 3 * Cc * Cc) {   // WmT[c, o] = Wm[o, c]
            int o = i % Cc; int c = i / Cc;
            g_WmT[c * Cc + o] = Wm[o * (3 * Cc) + c];
        }
    } else {
        // transpose: x[b,c,n,t] -> xT[s,n,c] (fp32 + fp16)
        if (threadIdx.x >= 192) return;
        const int bi = blk - 189;
        const int nb = bi & 31, cb = (bi >> 5) & 3, b = bi >> 7;
        const int c0 = cb * 16, n0 = nb * 16;
        const int tt_ = threadIdx.x;
        const int ni_l = tt_ / 12, tl = tt_ % 12;
        const int n_l = n0 + ni_l;
        #pragma unroll
        for (int ci = 0; ci < 16; ++ci) {
            float v = 0.f;
            if (n_l < Nn)
                v = x[(((size_t)b * Cc + c0 + ci) * Nn + n_l) * Tt + tl];
            sm[ci][tt_] = v;
        }
        __syncthreads();
        #pragma unroll
        for (int rep = 0; rep < 16; ++rep) {
            int idx = rep * 192 + tt_;
            int ci = idx & 15;
            int rest = idx >> 4;
            int ni = rest / 12, t = rest % 12;
            int n = n0 + ni;
            if (n < Nn) {
                size_t oi = (((size_t)(b * Tt + t) * Nn) + n) * Cc + c0 + ci;
                float v = sm[ci][rest];
                xT[oi] = v;
                g_xT16[oi] = __float2half_rn(v);
            }
        }
    }
}

// ================= fp16 HMMA projection GEMM (2 heads/block) + e-vec + Wh ===========
// grid (Ss, 8, 2), block 256 (8 warps). Tile 64 rows x 128 cols (heads 2z, 2z+1), K=64.
#define PAS_LD 72
#define PBS_LD 136
#define PCS_LD 132
__global__ void gemm_proj16(const __half* __restrict__ Ain,
                            const float* __restrict__ a1,
                            const float* __restrict__ a2) {
    __shared__ __align__(16) char smemRaw[64 * PCS_LD * 4];      // 33792 B
    __half (*As)[PAS_LD] = (__half(*)[PAS_LD])smemRaw;           // 9216 B
    __half (*Bs)[PBS_LD] = (__half(*)[PBS_LD])(smemRaw + 64 * PAS_LD * 2); // 17408 B
    float (*Cs)[PCS_LD] = (float(*)[PCS_LD])smemRaw;             // reuse after MMA

    const int s = blockIdx.x;
    const int r0 = blockIdx.y * 64;
    const int z = blockIdx.z;            // head pair
    const int c0 = z * 128;
    const int tid = threadIdx.x;
    const int wid = tid >> 5;
    const int wm = wid & 3, wn = wid >> 2;   // rows wm*16, cols wn*64
    const size_t rowB = (size_t)s * Nn;

    // stage A: 64 rows x 64 halfs (8 uint4/row), 2 uint4/thread
    {
        const uint4* srcA = (const uint4*)(Ain + rowB * Cc);
        #pragma unroll
        for (int k = 0; k < 2; ++k) {
            int idx = k * 256 + tid;
            int r = idx >> 3, p = idx & 7;
            int row = r0 + r;
            uint4 v = make_uint4(0, 0, 0, 0);
            if (row < Nn) v = srcA[(size_t)row * 8 + p];
            *(uint4*)&As[r][p * 8] = v;
        }
    }
    // stage B: Wcat16 rows 0..63, cols c0..c0+127 (16 uint4/row), 4 uint4/thread
    {
        const uint4* srcB = (const uint4*)(g_Wcat16 + c0);
        #pragma unroll
        for (int k = 0; k < 4; ++k) {
            int idx = k * 256 + tid;
            int r = idx >> 4, p = idx & 15;
            *(uint4*)&Bs[r][p * 8] = srcB[r * 32 + p];   // row stride 256 half = 32 uint4
        }
    }
    __syncthreads();

    wmma::fragment<wmma::accumulator, 16, 16, 16, float> fc[4];
    #pragma unroll
    for (int j = 0; j < 4; ++j) wmma::fill_fragment(fc[j], 0.f);
    #pragma unroll
    for (int k0 = 0; k0 < 64; k0 += 16) {
        wmma::fragment<wmma::matrix_a, 16, 16, 16, __half, wmma::row_major> fa;
        wmma::load_matrix_sync(fa, &As[wm * 16][k0], PAS_LD);
        #pragma unroll
        for (int j = 0; j < 4; ++j) {
            wmma::fragment<wmma::matrix_b, 16, 16, 16, __half, wmma::row_major> fb;
            wmma::load_matrix_sync(fb, &Bs[k0][wn * 64 + j * 16], PBS_LD);
            wmma::mma_sync(fc[j], fa, fb, fc[j]);
        }
    }
    __syncthreads();   // done reading As/Bs; reuse as Cs
    #pragma unroll
    for (int j = 0; j < 4; ++j)
        wmma::store_matrix_sync(&Cs[wm * 16][wn * 64 + j * 16], fc[j], PCS_LD,
                                wmma::mem_row_major);
    __syncthreads();

    // fused e-vec for both heads (interleaved [n][4] layout)
    {
        const int row = tid >> 2, q = tid & 3;
        #pragma unroll
        for (int hh = 0; hh < 2; ++hh) {
            const int hg = z * 2 + hh;           // global head
            float s1 = 0.f, s2 = 0.f;
            #pragma unroll
            for (int i = 0; i < 16; ++i) {
                int cl = hh * 64 + q * 16 + i;
                float v = Cs[row][cl];
                s1 = fmaf(v, a1[hg * Ff + q * 16 + i], s1);
                s2 = fmaf(v, a2[hg * Ff + q * 16 + i], s2);
            }
            s1 += __shfl_xor_sync(0xffffffffu, s1, 1);
            s2 += __shfl_xor_sync(0xffffffffu, s2, 1);
            s1 += __shfl_xor_sync(0xffffffffu, s1, 2);
            s2 += __shfl_xor_sync(0xffffffffu, s2, 2);
            if (q == 0 && r0 + row < Nn) {
                g_e1v[(rowB + r0 + row) * 4 + hg] = s1;
                g_e2v[(rowB + r0 + row) * 4 + hg] = s2;
            }
        }
    }

    // fp16 Wh store (coalesced): 64 rows x 64 half2
    __half2* dst = (__half2*)g_Wh16;
    #pragma unroll
    for (int k = 0; k < 16; ++k) {
        int idx = k * 256 + tid;
        int r = idx >> 6, p = idx & 63;
        if (r0 + r < Nn) {
            dst[(rowB + r0 + r) * (HF / 2) + z * 64 + p] =
                __floats2half2_rn(Cs[r][2 * p], Cs[r][2 * p + 1]);
        }
    }
}

// ---------------- attention: block (n,s), 128 thr; HFMA2 gather ----------------
__global__ void attn_agg() {
    const int n = blockIdx.x, s = blockIdx.y;
    const int t = threadIdx.x;
    const int h = t >> 5, lane = t & 31;
    __shared__ int snbr[MAXD];
    __shared__ __half swh[Hh][MAXD];
    __shared__ __half2 sred[4][32][4];     // [gatherWarp][chunk][pair]

    const int cnt = min(g_cnt[n], MAXD);
    for (int j = t; j < cnt; j += 128) snbr[j] = g_nbr[n * MAXD + j];
    __syncthreads();

    const size_t rowB = (size_t)s * Nn;
    // phase 1: softmax over neighbors for head h (warp h); e-vecs interleaved [n][4]
    const float e1v = g_e1v[(rowB + n) * 4 + h];
    float ev[4];
    float mx = -1e30f;
    #pragma unroll
    for (int k = 0; k < 4; ++k) {
        int j = k * 32 + lane;
        float e = -1e30f;
        if (j < cnt) {
            float tv = e1v + g_e2v[(rowB + snbr[j]) * 4 + h];
            e = tv > 0.f ? tv : LEAKc * tv;
        }
        ev[k] = e;
        mx = fmaxf(mx, e);
    }
    #pragma unroll
    for (int o = 16; o; o >>= 1) mx = fmaxf(mx, __shfl_xor_sync(0xffffffffu, mx, o));
    float sum = 0.f;
    #pragma unroll
    for (int k = 0; k < 4; ++k) {
        float w = (k * 32 + lane < cnt) ? __expf(ev[k] - mx) : 0.f;
        ev[k] = w;
        sum += w;
    }
    #pragma unroll
    for (int o = 16; o; o >>= 1) sum += __shfl_xor_sync(0xffffffffu, sum, o);
    const float inv = 1.f / sum;
    #pragma unroll
    for (int k = 0; k < 4; ++k) {
        int j = k * 32 + lane;
        if (j < cnt) swh[h][j] = __float2half_rn(ev[k] * inv);
    }
    __syncthreads();

    // phase 2: thread (g = t>>5, c = t&31); chunk c = 16B = 8 halfs; HFMA2 accumulate
    const int g = t >> 5, c = t & 31;
    const int hc = c >> 3;                 // head of this chunk
    const uint4* Whv = (const uint4*)g_Wh16;
    __half2 a0 = __float2half2_rn(0.f), a1h = a0, a2h = a0, a3h = a0;
    #pragma unroll 2
    for (int j0 = 0; j0 < cnt; j0 += 4) {
        int j = j0 + g;
        if (j < cnt) {
            int m = snbr[j];
            __half2 w2 = __half2half2(swh[hc][j]);
            uint4 v = Whv[(rowB + m) * 32 + c];
            a0 = __hfma2(*(__half2*)&v.x, w2, a0);
            a1h = __hfma2(*(__half2*)&v.y, w2, a1h);
            a2h = __hfma2(*(__half2*)&v.z, w2, a2h);
            a3h = __hfma2(*(__half2*)&v.w, w2, a3h);
        }
    }
    sred[g][c][0] = a0;
    sred[g][c][1] = a1h;
    sred[g][c][2] = a2h;
    sred[g][c][3] = a3h;
    __syncthreads();

    // reduce 4 partials in fp32, elu, fp16 store (thread t -> half pair t)
    const int rc = t >> 2, rp = t & 3;
    float2 v0 = __half22float2(sred[0][rc][rp]);
    float2 v1 = __half22float2(sred[1][rc][rp]);
    float2 v2 = __half22float2(sred[2][rc][rp]);
    float2 v3 = __half22float2(sred[3][rc][rp]);
    float vx = v0.x + v1.x + v2.x + v3.x;
    float vy = v0.y + v1.y + v2.y + v3.y;
    vx = vx > 0.f ? vx : (__expf(vx) - 1.f);
    vy = vy > 0.f ? vy : (__expf(vy) - 1.f);
    ((__half2*)g_hpr16)[(rowB + n) * (HF / 2) + t] = __floats2half2_rn(vx, vy);
}

// ================= fp16 wmma mix GEMM: h_next16 = a*x16 + (1-a)*(hpr16 @ WgT16 + bg) ==
// grid (Ss, 8), block 256 (8 warps). A fragments loaded straight from global.
#define MBS_LD 72
__global__ void gemm_mix_tc(const float* __restrict__ bias,
                            const __half* __restrict__ resid16,
                            __half* __restrict__ Cm16) {
    __shared__ __align__(16) char smemRaw[256 * MBS_LD * 2];   // Bs, reused as Cs
    __half (*Bs)[MBS_LD] = (__half(*)[MBS_LD])smemRaw;
    float (*Cs)[68] = (float(*)[68])smemRaw;                   // 17408 <= 36864

    const int s = blockIdx.x;
    const int r0 = blockIdx.y * 64;
    const int tid = threadIdx.x;
    const int wid = tid >> 5;
    const int wm = wid & 3, wn = wid >> 2;

    // stage B: 256 rows x 64 halfs (8 uint4/row), 8 uint4/thread
    {
        const uint4* src = (const uint4*)g_WgT16;
        #pragma unroll
        for (int k = 0; k < 8; ++k) {
            int idx = k * 256 + tid;
            int r = idx >> 3, p = idx & 7;
            *(uint4*)&Bs[r][p * 8] = src[r * 8 + p];
        }
    }
    __syncthreads();

    const __half* Aslice = g_hpr16 + (size_t)s * Nn * HF;      // padded tail -> safe OOB rows
    wmma::fragment<wmma::accumulator, 16, 16, 16, float> fc[2];
    wmma::fill_fragment(fc[0], 0.f);
    wmma::fill_fragment(fc[1], 0.f);
    #pragma unroll
    for (int k0 = 0; k0 < HF; k0 += 16) {
        wmma::fragment<wmma::matrix_a, 16, 16, 16, __half, wmma::row_major> fa;
        wmma::load_matrix_sync(fa, Aslice + (size_t)(r0 + wm * 16) * HF + k0, HF);
        #pragma unroll
        for (int sub = 0; sub < 2; ++sub) {
            wmma::fragment<wmma::matrix_b, 16, 16, 16, __half, wmma::row_major> fb;
            wmma::load_matrix_sync(fb, &Bs[k0][wn * 32 + sub * 16], MBS_LD);
            wmma::mma_sync(fc[sub], fa, fb, fc[sub]);
        }
    }
    __syncthreads();   // all warps done reading Bs; reuse as Cs
    wmma::store_matrix_sync(&Cs[wm * 16][wn * 32], fc[0], 68, wmma::mem_row_major);
    wmma::store_matrix_sync(&Cs[wm * 16][wn * 32 + 16], fc[1], 68, wmma::mem_row_major);
    __syncthreads();

    #pragma unroll
    for (int k = 0; k < 16; ++k) {
        int idx = k * 256 + tid;
        int r = idx >> 6, c = idx & 63;
        int row = r0 + r;
        if (row < Nn) {
            size_t oidx = ((size_t)s * Nn + row) * Cc + c;
            float v = ALPHAc * __half2float(resid16[oidx])
                    + (1.f - ALPHAc) * (Cs[r][c] + bias[c]);
            Cm16[oidx] = __float2half_rn(v);
        }
    }
}

// ---------------- final: out[b,o,n,t] = bm[o] + Wm @ [x; h1; h2] ----------------
__global__ void final_out(const float* __restrict__ xT,
                          const __half* __restrict__ h1,
                          const __half* __restrict__ h2,
                          const float* __restrict__ bm,
                          float* __restrict__ out) {
    __shared__ float sX[16][64], sH1[16][64], sH2[16][64];
    const int s = blockIdx.x;
    const int n0 = blockIdx.y * 16;
    const int tid = threadIdx.x;
    for (int i = tid; i < 16 * 64; i += 256) {
        int nl = i >> 6, c = i & 63;
        int n = n0 + nl;
        size_t idx = ((size_t)s * Nn + (n < Nn ? n : 0)) * Cc + c;
        sX[nl][c]  = (n < Nn) ? xT[idx] : 0.f;
        sH1[nl][c] = (n < Nn) ? __half2float(h1[idx]) : 0.f;
        sH2[nl][c] = (n < Nn) ? __half2float(h2[idx]) : 0.f;
    }
    __syncthreads();
    const int o = tid & 63, ng = tid >> 6;
    float acc[4] = {0.f, 0.f, 0.f, 0.f};
    #pragma unroll 4
    for (int c = 0; c < 64; ++c) {
        float w0 = g_WmT[c * Cc + o];
        float w1 = g_WmT[(64 + c) * Cc + o];
        float w2 = g_WmT[(128 + c) * Cc + o];
        #pragma unroll
        for (int r = 0; r < 4; ++r) {
            int nl = ng + r * 4;
            acc[r] = fmaf(w0, sX[nl][c], fmaf(w1, sH1[nl][c], fmaf(w2, sH2[nl][c], acc[r])));
        }
    }
    const int b = s / Tt, t = s % Tt;
    const float bias = bm[o];
    #pragma unroll
    for (int r = 0; r < 4; ++r) {
        int n = n0 + ng + r * 4;
        if (n < Nn)
            out[(((size_t)b * Cc + o) * Nn + n) * Tt + t] = acc[r] + bias;
    }
}

// ---------------- launch ----------------
extern "C" void kernel_launch(void* const* d_in, const int* in_sizes, int n_in,
                              void* d_out, int out_size) {
    const float* x   = (const float*)d_in[0];
    const float* adj = (const float*)d_in[1];
    const float* W   = (const float*)d_in[2];
    const float* a1  = (const float*)d_in[3];
    const float* a2  = (const float*)d_in[4];
    const float* Wg  = (const float*)d_in[5];
    const float* bg  = (const float*)d_in[6];
    const float* Wm  = (const float*)d_in[7];
    const float* bm  = (const float*)d_in[8];
    float* out = (float*)d_out;

    float* xT;
    __half *xT16, *h1T16, *h2T16;
    cudaGetSymbolAddress((void**)&xT,    g_xT);
    cudaGetSymbolAddress((void**)&xT16,  g_xT16);
    cudaGetSymbolAddress((void**)&h1T16, g_h1T16);
    cudaGetSymbolAddress((void**)&h2T16, g_h2T16);

    prep_all<<<1213, 256>>>(adj, W, Wg, Wm, x, xT);

    const __half* hin16 = xT16;
    __half* hb16[2] = {h1T16, h2T16};
    for (int it = 0; it < 2; ++it) {
        gemm_proj16<<<dim3(Ss, 8, 2), 256>>>(hin16, a1, a2);
        attn_agg<<<dim3(Nn, Ss), 128>>>();
        gemm_mix_tc<<<dim3(Ss, 8), 256>>>(bg, xT16, hb16[it]);
        hin16 = hb16[it];
    }
    final_out<<<dim3(Ss, (Nn + 15) / 16), 256>>>(xT, h1T16, h2T16, bm, out);
}